// round 8
// baseline (speedup 1.0000x reference)
#include <cuda_runtime.h>
#include <cstdint>

#define NT 256
#define PX 136            // X smem row pitch (floats), conflict-free
#define XSTG (32 * PX)    // 4352
#define WSTG 2048         // 64ch x 32k per stage
#define STG  (XSTG + WSTG)  // 6400 floats per stage

// Pre-swizzled, rna-tf32, truncation-compensated weights.
// Per scale, per ntile(64ch), per ktile(32k, 2048 floats):
//   idx = kkb*512 + cg*128 + g*16 + tg*4 + i
//   ch = nt*64 + cg*16 + g + (i&1)*8 ;  k = kt*32 + kkb*8 + tg + (i>>1)*4
// scale sizes: K*256 floats -> 65536 + 131072 + 262144 = 458752
__device__ float g_wswz[458752];

__device__ __forceinline__ void cp16(uint32_t dst, const float* src, bool pred) {
    asm volatile("cp.async.ca.shared.global [%0], [%1], 16, %2;\n"
                 :: "r"(dst), "l"(__cvta_generic_to_global(src)),
                    "r"(pred ? 16 : 0));
}

__device__ __forceinline__ void mma_tf32(float d[4], const uint32_t a[4],
                                         const uint32_t b[2], const float c[4]) {
    asm volatile(
        "mma.sync.aligned.m16n8k8.row.col.f32.tf32.tf32.f32 "
        "{%0,%1,%2,%3}, {%4,%5,%6,%7}, {%8,%9}, {%10,%11,%12,%13};"
        : "=f"(d[0]), "=f"(d[1]), "=f"(d[2]), "=f"(d[3])
        : "r"(a[0]), "r"(a[1]), "r"(a[2]), "r"(a[3]),
          "r"(b[0]), "r"(b[1]),
          "f"(c[0]), "f"(c[1]), "f"(c[2]), "f"(c[3]));
}

// ---------------- W prep: rna-tf32 + compensation + fragment swizzle ---------
__global__ void yolo_prep(const float* __restrict__ w0,
                          const float* __restrict__ w1,
                          const float* __restrict__ w2) {
    int idx = blockIdx.x * NT + threadIdx.x;
    if (idx >= 458752) return;
    const float* w; int K, base;
    if (idx < 65536)       { w = w0; K = 256;  base = 0; }
    else if (idx < 196608) { w = w1; K = 512;  base = 65536; }
    else                   { w = w2; K = 1024; base = 196608; }
    int r = idx - base;
    int nt = r / (K * 64); r -= nt * (K * 64);
    int kt  = r >> 11; r &= 2047;
    int kkb = r >> 9;  r &= 511;
    int cg  = r >> 7;  r &= 127;
    int g   = r >> 4;  r &= 15;
    int tg  = r >> 2;  int i = r & 3;
    int n = nt * 64 + cg * 16 + g + (i & 1) * 8;
    int k = kt * 32 + kkb * 8 + tg + (i >> 1) * 4;
    float v = 0.f;
    if (n < 255) {
        float x = w[n * K + k] * 1.000352f;   // compensate X-truncation shrink
        uint32_t u;
        asm("cvt.rna.tf32.f32 %0, %1;" : "=r"(u) : "f"(x));
        v = __uint_as_float(u);
    }
    g_wswz[idx] = v;
}

// ---------------- fused main: 3 scales, GEMM + decode ------------------------
// CTA tile: 64 channels x 128 spatial, BK=32. 8 warps = 2(ch) x 4(sp),
// warp tile 32ch x 32sp (2mi x 4ni). MMA: A=W (m16=ch), B=X (n8=spatial),
// spatial mapping m = sp*32 + g*4 + ni so B loads are LDS.128.
// cp.async pipeline with prefetch distance 2 over a 2-stage smem ring.
__global__ __launch_bounds__(NT, 3)
void yolo_main(const float* __restrict__ p0, const float* __restrict__ p1,
               const float* __restrict__ p2,
               const float* __restrict__ bb0, const float* __restrict__ bb1,
               const float* __restrict__ bb2,
               const float* __restrict__ anchors, float* __restrict__ out) {
    extern __shared__ float smem[];   // 2 stages x STG floats
    __shared__ float sbias[64];

    const int tid = threadIdx.x;
    const int bx  = blockIdx.x;
    const int nt  = blockIdx.y;      // 0..3 (64-ch tiles)
    const int b   = blockIdx.z;

    const float* p; const float* bias; const float* anc;
    int K, S, nx, sh, mt, sbase, woff; float strd;
    if (bx < 50)      { p=p0; bias=bb0; anc=anchors;      K=256;  S=6400; nx=80; sh=6; mt=bx;    sbase=0;     woff=0;      strd=8.f;  }
    else if (bx < 63) { p=p1; bias=bb1; anc=anchors+6;    K=512;  S=1600; nx=40; sh=5; mt=bx-50; sbase=19200; woff=65536;  strd=16.f; }
    else              { p=p2; bias=bb2; anc=anchors+12;   K=1024; S=400;  nx=20; sh=4; mt=bx-63; sbase=24000; woff=196608; strd=32.f; }

    const int m0 = mt * 128;
    const int n0 = nt * 64;

    if (tid < 64) sbias[tid] = (n0 + tid < 255) ? bias[n0 + tid] : 0.f;

    // ---- async loaders ----
    const int  xm = (tid & 31) * 4;        // spatial (4 floats)
    const int  xk = tid >> 5;              // k row base (rows xk+8i)
    const bool xv = (m0 + xm) < S;
    const float* xg = p + (size_t)b * K * S + (size_t)xk * S + (m0 + xm);
    const float* wg = g_wswz + woff + nt * (K * 64) + tid * 8;

    const uint32_t sb = (uint32_t)__cvta_generic_to_shared(smem);
    const int nk = K >> 5;

    auto issue = [&](int tt, int ss) {
        const float* xs = xg + (size_t)(tt << 5) * S;
        const uint32_t xb = sb + (uint32_t)(ss * STG + xm) * 4u;
#pragma unroll
        for (int i = 0; i < 4; ++i)
            cp16(xb + (uint32_t)((xk + 8 * i) * PX) * 4u,
                 xs + (size_t)(8 * i) * S, xv);
        const float* ws = wg + tt * WSTG;
        const uint32_t wb = sb + (uint32_t)(ss * STG + XSTG + tid * 8) * 4u;
        cp16(wb,      ws,     true);
        cp16(wb + 16, ws + 4, true);
        asm volatile("cp.async.commit_group;\n");
    };

    const int lane = tid & 31, wid = tid >> 5;
    const int c  = wid >> 2;   // channel half (0..1) -> 32ch
    const int sp = wid & 3;    // spatial quarter (0..3) -> 32sp
    const int g  = lane >> 2, tg = lane & 3;

    float acc[2][4][4];
#pragma unroll
    for (int mi = 0; mi < 2; ++mi)
#pragma unroll
        for (int ni = 0; ni < 4; ++ni)
#pragma unroll
            for (int r = 0; r < 4; ++r) acc[mi][ni][r] = 0.f;

    // distance-2 prefetch: both stages in flight before the loop (nk >= 8)
    issue(0, 0);
    issue(1, 1);

    for (int t = 0; t < nk; ++t) {
        if (t + 1 < nk) asm volatile("cp.async.wait_group 1;\n" ::: "memory");
        else            asm volatile("cp.async.wait_group 0;\n" ::: "memory");
        __syncthreads();

        const float* st = smem + (t & 1) * STG;
        const uint32_t* Xs = (const uint32_t*)st;
        const uint32_t* Ws = (const uint32_t*)(st + XSTG);

#pragma unroll
        for (int kkb = 0; kkb < 4; ++kkb) {
            uint4 av[2];
#pragma unroll
            for (int mi = 0; mi < 2; ++mi)
                av[mi] = *(const uint4*)(Ws + kkb * 512 + (c * 2 + mi) * 128 +
                                         g * 16 + tg * 4);
            const uint4 b0 = *(const uint4*)(Xs + (kkb * 8 + tg) * PX + sp * 32 + g * 4);
            const uint4 b1 = *(const uint4*)(Xs + (kkb * 8 + tg + 4) * PX + sp * 32 + g * 4);
            const uint32_t bf[4][2] = {{b0.x, b1.x}, {b0.y, b1.y},
                                       {b0.z, b1.z}, {b0.w, b1.w}};
#pragma unroll
            for (int mi = 0; mi < 2; ++mi)
#pragma unroll
                for (int ni = 0; ni < 4; ++ni)
                    mma_tf32(acc[mi][ni], (const uint32_t*)&av[mi], bf[ni],
                             acc[mi][ni]);
        }
        __syncthreads();
        if (t + 2 < nk) issue(t + 2, t & 1);   // refill the stage just drained
    }

    // ---- fused epilogue: bias + sigmoid + YOLO decode ----
    const size_t ob = (size_t)b * 25200 + sbase;
#pragma unroll
    for (int mi = 0; mi < 2; ++mi)
#pragma unroll
        for (int ni = 0; ni < 4; ++ni)
#pragma unroll
            for (int r = 0; r < 4; ++r) {
                const int n = n0 + c * 32 + mi * 16 + g + ((r & 2) ? 8 : 0);
                const int m = m0 + sp * 32 + (tg * 2 + (r & 1)) * 4 + ni;
                if (n < 255 && m < S) {
                    const float v  = acc[mi][ni][r] + sbias[n - n0];
                    const float sg = 1.f / (1.f + __expf(-v));
                    const int a  = (n * 772) >> 16;   // n / 85 for n < 255
                    const int no = n - a * 85;
                    float ov;
                    if (no < 2) {
                        const int y = (int)(__umulhi((unsigned)m, 3435973837u) >> sh);
                        const int gc = (no == 0) ? (m - y * nx) : y;
                        ov = (2.f * sg + (float)gc - 0.5f) * strd;
                    } else if (no < 4) {
                        const float t2 = 2.f * sg;
                        ov = t2 * t2 * __ldg(anc + a * 2 + (no - 2));
                    } else {
                        ov = sg;
                    }
                    out[(ob + (size_t)a * S + m) * 85 + no] = ov;
                }
            }
}

extern "C" void kernel_launch(void* const* d_in, const int* in_sizes, int n_in,
                              void* d_out, int out_size) {
    const float* p0 = (const float*)d_in[0];
    const float* p1 = (const float*)d_in[1];
    const float* p2 = (const float*)d_in[2];
    const float* w0 = (const float*)d_in[3];
    const float* b0 = (const float*)d_in[4];
    const float* w1 = (const float*)d_in[5];
    const float* b1 = (const float*)d_in[6];
    const float* w2 = (const float*)d_in[7];
    const float* b2 = (const float*)d_in[8];
    const float* anc = (const float*)d_in[9];
    float* out = (float*)d_out;

    cudaFuncSetAttribute(yolo_main, cudaFuncAttributeMaxDynamicSharedMemorySize,
                         2 * STG * 4);

    yolo_prep<<<1792, NT>>>(w0, w1, w2);
    // m-tiles: 50 (80x80) + 13 (40x40) + 4 (20x20) = 67 ; n-tiles: 4 x 64ch
    yolo_main<<<dim3(67, 4, 16), NT, 2 * STG * 4>>>(p0, p1, p2, b0, b1, b2,
                                                    anc, out);
}

// round 9
// speedup vs baseline: 1.2445x; 1.2445x over previous
#include <cuda_runtime.h>
#include <cstdint>

#define NT 256
#define XPITCH 136               // words (bf16x2) per X smem row
#define XSTGW (16 * XPITCH)      // 2176 words per X stage (16 k-pair rows)
#define WSTGW 1024               // words per W stage (64ch x 32k bf16)
#define SMEM_WORDS (2 * XSTGW + 3 * WSTGW)   // 7424 words = 29696 B

// Pre-packed bf16 weight fragment images.
// Per scale, per ntile(64ch), per ktile(32k): 1024 words:
//   word = kkb*512 + cg*128 + g*16 + tg*4 + j
//   ch = nt*64 + cg*16 + g + (j&1)*8 ; k = kt*32 + kkb*16 + (j>>1)*8 + tg*2
//   word packs {bf16(W[ch][k]) lo, bf16(W[ch][k+1]) hi}
// totals (words): 32768 + 65536 + 131072 = 229376
__device__ uint32_t g_wswz[229376];

__device__ __forceinline__ void cp16(uint32_t dst, const void* src) {
    asm volatile("cp.async.cg.shared.global [%0], [%1], 16;\n"
                 :: "r"(dst), "l"(__cvta_generic_to_global(src)));
}

__device__ __forceinline__ uint32_t packbf(float lo, float hi) {
    uint32_t v;
    asm("cvt.rn.bf16x2.f32 %0, %1, %2;" : "=r"(v) : "f"(hi), "f"(lo));
    return v;
}

__device__ __forceinline__ void mma_bf16(float d[4], const uint32_t a[4],
                                         const uint32_t b[2], const float c[4]) {
    asm volatile(
        "mma.sync.aligned.m16n8k16.row.col.f32.bf16.bf16.f32 "
        "{%0,%1,%2,%3}, {%4,%5,%6,%7}, {%8,%9}, {%10,%11,%12,%13};"
        : "=f"(d[0]), "=f"(d[1]), "=f"(d[2]), "=f"(d[3])
        : "r"(a[0]), "r"(a[1]), "r"(a[2]), "r"(a[3]),
          "r"(b[0]), "r"(b[1]),
          "f"(c[0]), "f"(c[1]), "f"(c[2]), "f"(c[3]));
}

// ---------------- W prep: bf16 pack + fragment swizzle -----------------------
__global__ void yolo_prep(const float* __restrict__ w0,
                          const float* __restrict__ w1,
                          const float* __restrict__ w2) {
    int idx = blockIdx.x * NT + threadIdx.x;
    if (idx >= 229376) return;
    const float* w; int K, base;
    if (idx < 32768)      { w = w0; K = 256;  base = 0; }
    else if (idx < 98304) { w = w1; K = 512;  base = 32768; }
    else                  { w = w2; K = 1024; base = 98304; }
    int r = idx - base;
    int nt = r / (K * 32); r -= nt * (K * 32);
    int kt  = r >> 10; r &= 1023;
    int kkb = r >> 9;  r &= 511;
    int cg  = r >> 7;  r &= 127;
    int g   = r >> 4;  r &= 15;
    int tg  = r >> 2;  int j = r & 3;
    int ch = nt * 64 + cg * 16 + g + (j & 1) * 8;
    int k  = kt * 32 + kkb * 16 + (j >> 1) * 8 + tg * 2;
    uint32_t v = 0;
    if (ch < 255) v = packbf(w[ch * K + k], w[ch * K + k + 1]);
    g_wswz[idx] = v;
}

// ---------------- fused main: 3 scales, bf16 GEMM + decode -------------------
// CTA 64ch x 128sp, BK=32. 8 warps = 2(ch) x 4(sp), warp 32x32 (2mi x 4ni).
// MMA m16n8k16: A=W(ch), B=X(sp); spatial map m = sp*32 + v*4 + ni.
// X smem: rows = k-pairs (16/ktile), cols = m words, bit5-XOR swizzled.
__global__ __launch_bounds__(NT, 3)
void yolo_main(const float* __restrict__ p0, const float* __restrict__ p1,
               const float* __restrict__ p2,
               const float* __restrict__ bb0, const float* __restrict__ bb1,
               const float* __restrict__ bb2,
               const float* __restrict__ anchors, float* __restrict__ out) {
    __shared__ uint32_t smem[SMEM_WORDS];
    __shared__ float sbias[64];

    const int tid = threadIdx.x;
    const int bx  = blockIdx.x;
    const int nt  = blockIdx.y;      // 0..3 (64-ch tiles)
    const int b   = blockIdx.z;

    const float* p; const float* bias; const float* anc;
    int K, S, nx, sh, mt, sbase, woff; float strd;
    if (bx < 50)      { p=p0; bias=bb0; anc=anchors;      K=256;  S=6400; nx=80; sh=6; mt=bx;    sbase=0;     woff=0;     strd=8.f;  }
    else if (bx < 63) { p=p1; bias=bb1; anc=anchors+6;    K=512;  S=1600; nx=40; sh=5; mt=bx-50; sbase=19200; woff=32768; strd=16.f; }
    else              { p=p2; bias=bb2; anc=anchors+12;   K=1024; S=400;  nx=20; sh=4; mt=bx-63; sbase=24000; woff=98304; strd=32.f; }

    const int m0 = mt * 128;
    const int n0 = nt * 64;
    const int nk = K >> 5;

    if (tid < 64) sbias[tid] = (n0 + tid < 255) ? bias[n0 + tid] : 0.f;

    // ---- X loader thread constants ----
    const int kp  = tid >> 4;          // 0..15 (k-pair row)
    const int mq0 = (tid & 15) * 2;    // first m-quad (0..30)
    const bool v0 = (m0 + mq0 * 4) < S;
    const bool v1 = (m0 + mq0 * 4 + 4) < S;
    const float* pb = p + (size_t)b * K * S + m0;
    // ---- W loader ----
    const uint32_t* wg = g_wswz + woff + (size_t)nt * (K * 32) + tid * 4;
    const uint32_t sb = (uint32_t)__cvta_generic_to_shared(smem);

    // swizzled STS columns (constant per thread)
    const int c0raw = mq0 * 4;
    const int c1raw = c0raw + 4;
    const int sc0 = c0raw ^ (((c0raw >> 5) & 1) << 2);
    const int sc1 = c1raw ^ (((c1raw >> 5) & 1) << 2);

    // ---- MMA thread constants ----
    const int lane = tid & 31, wid = tid >> 5;
    const int c  = wid >> 2;   // channel half
    const int sp = wid & 3;    // spatial quarter
    const int g  = lane >> 2, tg = lane & 3;
    const int aoff = (c * 2) * 128 + g * 16 + tg * 4;              // + mi*128, +kkb*512
    const int boff = (sp * 32 + g * 4) ^ ((sp & 1) << 2);          // swizzle folded

    float acc[2][4][4];
#pragma unroll
    for (int mi = 0; mi < 2; ++mi)
#pragma unroll
        for (int ni = 0; ni < 4; ++ni)
#pragma unroll
            for (int r = 0; r < 4; ++r) acc[mi][ni][r] = 0.f;

    float4 xr[4];
    const float4 z4 = make_float4(0.f, 0.f, 0.f, 0.f);

    // prologue: W groups 0,1 in flight; X tile 0 in regs
    {
        const uint32_t wdst0 = sb + (uint32_t)(2 * XSTGW) * 4u + (uint32_t)tid * 16u;
        cp16(wdst0, wg);
        asm volatile("cp.async.commit_group;\n");
        if (nk > 1) {
            cp16(wdst0 + WSTGW * 4u, wg + WSTGW);
            asm volatile("cp.async.commit_group;\n");
        }
        const float* src = pb + (size_t)(kp * 2) * S;
        xr[0] = v0 ? *(const float4*)(src + c0raw)     : z4;
        xr[1] = v0 ? *(const float4*)(src + S + c0raw) : z4;
        xr[2] = v1 ? *(const float4*)(src + c1raw)     : z4;
        xr[3] = v1 ? *(const float4*)(src + S + c1raw) : z4;
    }

    int wst = 0;   // W stage of tile t (t % 3)
    for (int t = 0; t < nk; ++t) {
        // A) convert + store X tile t
        {
            uint32_t* xs = smem + (t & 1) * XSTGW + kp * XPITCH;
            uint4 w0q, w1q;
            w0q.x = packbf(xr[0].x, xr[1].x); w0q.y = packbf(xr[0].y, xr[1].y);
            w0q.z = packbf(xr[0].z, xr[1].z); w0q.w = packbf(xr[0].w, xr[1].w);
            w1q.x = packbf(xr[2].x, xr[3].x); w1q.y = packbf(xr[2].y, xr[3].y);
            w1q.z = packbf(xr[2].z, xr[3].z); w1q.w = packbf(xr[2].w, xr[3].w);
            *(uint4*)(xs + sc0) = w0q;
            *(uint4*)(xs + sc1) = w1q;
        }
        // B) W tile t ready
        if (t + 1 < nk) asm volatile("cp.async.wait_group 1;\n" ::: "memory");
        else            asm volatile("cp.async.wait_group 0;\n" ::: "memory");
        // C)
        __syncthreads();
        // D) issue next loads
        if (t + 2 < nk) {
            int ws2 = wst + 2; if (ws2 >= 3) ws2 -= 3;
            cp16(sb + (uint32_t)(2 * XSTGW + ws2 * WSTGW) * 4u + (uint32_t)tid * 16u,
                 wg + (size_t)(t + 2) * WSTGW);
            asm volatile("cp.async.commit_group;\n");
        }
        if (t + 1 < nk) {
            const float* src = pb + (size_t)((t + 1) * 32 + kp * 2) * S;
            xr[0] = v0 ? *(const float4*)(src + c0raw)     : z4;
            xr[1] = v0 ? *(const float4*)(src + S + c0raw) : z4;
            xr[2] = v1 ? *(const float4*)(src + c1raw)     : z4;
            xr[3] = v1 ? *(const float4*)(src + S + c1raw) : z4;
        }
        // E) MMAs on tile t
        const uint32_t* Xs = smem + (t & 1) * XSTGW;
        const uint32_t* Ws = smem + 2 * XSTGW + wst * WSTGW;
#pragma unroll
        for (int kkb = 0; kkb < 2; ++kkb) {
            uint4 av[2];
#pragma unroll
            for (int mi = 0; mi < 2; ++mi)
                av[mi] = *(const uint4*)(Ws + kkb * 512 + aoff + mi * 128);
            const uint4 bq0 = *(const uint4*)(Xs + (kkb * 8 + tg) * XPITCH + boff);
            const uint4 bq1 = *(const uint4*)(Xs + (kkb * 8 + tg + 4) * XPITCH + boff);
            const uint32_t bf[4][2] = {{bq0.x, bq1.x}, {bq0.y, bq1.y},
                                       {bq0.z, bq1.z}, {bq0.w, bq1.w}};
#pragma unroll
            for (int mi = 0; mi < 2; ++mi)
#pragma unroll
                for (int ni = 0; ni < 4; ++ni)
                    mma_bf16(acc[mi][ni], (const uint32_t*)&av[mi], bf[ni],
                             acc[mi][ni]);
        }
        if (++wst == 3) wst = 0;
    }

    // ---- fused epilogue: bias + sigmoid + YOLO decode ----
    const size_t ob = (size_t)b * 25200 + sbase;
#pragma unroll
    for (int mi = 0; mi < 2; ++mi)
#pragma unroll
        for (int ni = 0; ni < 4; ++ni)
#pragma unroll
            for (int r = 0; r < 4; ++r) {
                const int n = n0 + c * 32 + mi * 16 + g + ((r & 2) ? 8 : 0);
                const int m = m0 + sp * 32 + (tg * 2 + (r & 1)) * 4 + ni;
                if (n < 255 && m < S) {
                    const float v  = acc[mi][ni][r] + sbias[n - n0];
                    const float sg = 1.f / (1.f + __expf(-v));
                    const int a  = (n * 772) >> 16;   // n / 85 for n < 255
                    const int no = n - a * 85;
                    float ov;
                    if (no < 2) {
                        const int y = (int)(__umulhi((unsigned)m, 3435973837u) >> sh);
                        const int gc = (no == 0) ? (m - y * nx) : y;
                        ov = (2.f * sg + (float)gc - 0.5f) * strd;
                    } else if (no < 4) {
                        const float t2 = 2.f * sg;
                        ov = t2 * t2 * __ldg(anc + a * 2 + (no - 2));
                    } else {
                        ov = sg;
                    }
                    out[(ob + (size_t)a * S + m) * 85 + no] = ov;
                }
            }
}

extern "C" void kernel_launch(void* const* d_in, const int* in_sizes, int n_in,
                              void* d_out, int out_size) {
    const float* p0 = (const float*)d_in[0];
    const float* p1 = (const float*)d_in[1];
    const float* p2 = (const float*)d_in[2];
    const float* w0 = (const float*)d_in[3];
    const float* b0 = (const float*)d_in[4];
    const float* w1 = (const float*)d_in[5];
    const float* b1 = (const float*)d_in[6];
    const float* w2 = (const float*)d_in[7];
    const float* b2 = (const float*)d_in[8];
    const float* anc = (const float*)d_in[9];
    float* out = (float*)d_out;

    yolo_prep<<<896, NT>>>(w0, w1, w2);
    // m-tiles: 50 (80x80) + 13 (40x40) + 4 (20x20) = 67 ; n-tiles: 4 x 64ch
    yolo_main<<<dim3(67, 4, 16), NT>>>(p0, p1, p2, b0, b1, b2, anc, out);
}